// round 4
// baseline (speedup 1.0000x reference)
#include <cuda_runtime.h>
#include <cstddef>

#define N_NODES 100000
#define N_EDGES 600000
#define FEAT    128
#define OUTD    64

// ---------------- scratch (device globals; no allocation allowed) ----------
__device__ __align__(128) float g_bufA[(size_t)N_NODES * FEAT];
__device__ __align__(128) float g_bufB[(size_t)N_NODES * FEAT];
__device__ __align__(128) float g_hn  [(size_t)N_NODES * FEAT];
__device__ int g_deg[N_NODES];
__device__ int g_rowptr[N_NODES + 1];
__device__ int g_cursor[N_NODES];
__device__ int g_csr[N_EDGES];

// buffer selectors (resolved device-side; keeps kernel_launch API-free)
#define BUF_EXT 0   // use the passed-in external pointer
#define BUF_A   1
#define BUF_B   2

__device__ __forceinline__ const float* sel_src(int sel, const float* ext) {
    if (sel == BUF_A) return g_bufA;
    if (sel == BUF_B) return g_bufB;
    return ext;
}
__device__ __forceinline__ float* sel_dst(int sel, float* ext) {
    if (sel == BUF_A) return g_bufA;
    if (sel == BUF_B) return g_bufB;
    return ext;
}

// ---------------- small helpers -------------------------------------------
__device__ __forceinline__ unsigned long long pack2(float a, float b) {
    unsigned long long r;
    asm("mov.b64 %0, {%1,%2};" : "=l"(r) : "f"(a), "f"(b));
    return r;
}
__device__ __forceinline__ void ffma2(unsigned long long& d,
                                      unsigned long long a,
                                      unsigned long long b) {
    asm("fma.rn.f32x2 %0, %1, %2, %0;" : "+l"(d) : "l"(a), "l"(b));
}

// ---------------- CSR construction ----------------------------------------
__global__ void k_zero_deg() {
    int i = blockIdx.x * blockDim.x + threadIdx.x;
    if (i < N_NODES) g_deg[i] = 0;
}

__global__ void k_count(const int* __restrict__ dst) {
    int e = blockIdx.x * blockDim.x + threadIdx.x;
    if (e < N_EDGES) atomicAdd(&g_deg[dst[e]], 1);
}

// single-block exclusive scan of deg -> rowptr (and cursor copy)
__global__ void k_scan() {
    __shared__ int sh[1024];
    __shared__ int carry;
    int tid = threadIdx.x;
    if (tid == 0) carry = 0;
    __syncthreads();
    for (int base = 0; base < N_NODES; base += 1024) {
        int i = base + tid;
        int v = (i < N_NODES) ? g_deg[i] : 0;
        sh[tid] = v;
        __syncthreads();
        for (int off = 1; off < 1024; off <<= 1) {
            int t = (tid >= off) ? sh[tid - off] : 0;
            __syncthreads();
            sh[tid] += t;
            __syncthreads();
        }
        int excl = sh[tid] - v + carry;
        if (i < N_NODES) { g_rowptr[i] = excl; g_cursor[i] = excl; }
        __syncthreads();
        if (tid == 0) carry += sh[1023];
        __syncthreads();
    }
    if (tid == 0) g_rowptr[N_NODES] = carry;
}

__global__ void k_fill(const int* __restrict__ src, const int* __restrict__ dst) {
    int e = blockIdx.x * blockDim.x + threadIdx.x;
    if (e < N_EDGES) {
        int p = atomicAdd(&g_cursor[dst[e]], 1);
        g_csr[p] = src[e];
    }
}

// ---------------- neighbor mean aggregation (warp per node) ----------------
__global__ void k_aggregate(int h_sel, const float* __restrict__ h_ext) {
    const float* __restrict__ h = sel_src(h_sel, h_ext);
    int node = (blockIdx.x * blockDim.x + threadIdx.x) >> 5;
    if (node >= N_NODES) return;
    int lane = threadIdx.x & 31;
    int beg = g_rowptr[node], end = g_rowptr[node + 1];
    float4 acc = make_float4(0.f, 0.f, 0.f, 0.f);
    for (int e = beg; e < end; e++) {
        int s = g_csr[e];
        float4 v = ((const float4*)(h + (size_t)s * FEAT))[lane];
        acc.x += v.x; acc.y += v.y; acc.z += v.z; acc.w += v.w;
    }
    float inv = 1.0f / fmaxf((float)(end - beg), 1.0f);
    acc.x *= inv; acc.y *= inv; acc.z *= inv; acc.w *= inv;
    ((float4*)(g_hn + (size_t)node * FEAT))[lane] = acc;
}

// ---------------- fused (dual-)GEMM + bias (+ReLU) -------------------------
// C[M,N] = act( A1@B1 (+ hn@B2) + bias1 (+ bias2) )
// B matrices are [K, N] row-major. Requires BN == N.
template <int KTOT, int N, int BM, int BN, int BK, int TM, int TN, bool DUAL, bool RELU>
__global__ __launch_bounds__(256)
void k_gemm(int a1_sel, const float* __restrict__ A1_ext,
            const float* __restrict__ B1, const float* __restrict__ B2,
            const float* __restrict__ bias1, const float* __restrict__ bias2,
            int c_sel, float* __restrict__ C_ext, int M) {
    constexpr int K  = DUAL ? KTOT / 2 : KTOT;   // per-matrix K
    constexpr int TX = BN / TN;                   // threads along n
    constexpr int TY = BM / TM;                   // threads along m
    static_assert(TX * TY == 256, "thread count mismatch");
    static_assert(BN == N, "BN must equal N");
    static_assert(K % BK == 0, "K % BK");

    const float* __restrict__ A1 = sel_src(a1_sel, A1_ext);
    float* __restrict__ C = sel_dst(c_sel, C_ext);

    __shared__ __align__(16) float As[BK * BM];   // As[k][m]
    __shared__ __align__(16) float Bs[BK * BN];   // Bs[k][n]

    const int tid = threadIdx.x;
    const int tx = tid % TX, ty = tid / TX;
    const int row0 = blockIdx.x * BM;

    unsigned long long acc[TM][TN / 2];
#pragma unroll
    for (int m = 0; m < TM; m++)
#pragma unroll
        for (int j = 0; j < TN / 2; j++) acc[m][j] = 0ull;

#pragma unroll 1
    for (int k0 = 0; k0 < KTOT; k0 += BK) {
        const bool first = (!DUAL) || (k0 < K);
        const float* __restrict__ A = first ? A1 : (const float*)g_hn;
        const float* __restrict__ B = first ? B1 : B2;
        const int ka = first ? k0 : (k0 - K);

        // A tile: BM x BK -> As (k-major). 4 lanes per row, 16B per lane.
#pragma unroll
        for (int i = 0; i < (BM * BK / 4) / 256; i++) {
            int idx = i * 256 + tid;
            int kq  = idx & 3;        // which float4 within the BK=16 chunk
            int row = idx >> 2;       // 0..BM-1
            float4 v = make_float4(0.f, 0.f, 0.f, 0.f);
            if (row0 + row < M)
                v = *(const float4*)(A + (size_t)(row0 + row) * K + ka + kq * 4);
            As[(kq * 4 + 0) * BM + row] = v.x;
            As[(kq * 4 + 1) * BM + row] = v.y;
            As[(kq * 4 + 2) * BM + row] = v.z;
            As[(kq * 4 + 3) * BM + row] = v.w;
        }
        // B tile: BK x BN, coalesced, row stride N
#pragma unroll
        for (int i = 0; i < (BK * BN / 4) / 256; i++) {
            int idx = i * 256 + tid;
            int kr  = idx / (BN / 4);
            int n4  = idx % (BN / 4);
            float4 v = *(const float4*)(B + (size_t)(ka + kr) * N + n4 * 4);
            ((float4*)Bs)[idx] = v;
        }
        __syncthreads();

#pragma unroll
        for (int k = 0; k < BK; k++) {
            // a fragment: TM scalars, duplicated into f32x2 pairs
            unsigned long long ap[TM];
#pragma unroll
            for (int q = 0; q < TM / 4; q++) {
                float4 a4 = *(const float4*)&As[k * BM + ty * TM + 4 * q];
                ap[4 * q + 0] = pack2(a4.x, a4.x);
                ap[4 * q + 1] = pack2(a4.y, a4.y);
                ap[4 * q + 2] = pack2(a4.z, a4.z);
                ap[4 * q + 3] = pack2(a4.w, a4.w);
            }
            // b fragment: consecutive float pairs ARE packed f32x2 (free)
            unsigned long long bp[TN / 2];
#pragma unroll
            for (int j = 0; j < TN / 4; j++) {
                ulonglong2 t = *(const ulonglong2*)&Bs[k * BN + tx * TN + 4 * j];
                bp[2 * j + 0] = t.x;
                bp[2 * j + 1] = t.y;
            }
#pragma unroll
            for (int m = 0; m < TM; m++)
#pragma unroll
                for (int j = 0; j < TN / 2; j++)
                    ffma2(acc[m][j], ap[m], bp[j]);
        }
        __syncthreads();
    }

    // epilogue: bias (+relu), packed float2 stores
    float bs[TN];
#pragma unroll
    for (int t = 0; t < TN; t++) {
        int col = tx * TN + t;
        bs[t] = bias1[col] + (DUAL ? bias2[col] : 0.0f);
    }
#pragma unroll
    for (int m = 0; m < TM; m++) {
        int grow = row0 + ty * TM + m;
        if (grow < M) {
#pragma unroll
            for (int j = 0; j < TN / 2; j++) {
                union { unsigned long long u; float2 f; } cv;
                cv.u = acc[m][j];
                float x = cv.f.x + bs[2 * j];
                float y = cv.f.y + bs[2 * j + 1];
                if (RELU) { x = fmaxf(x, 0.f); y = fmaxf(y, 0.f); }
                *(float2*)(C + (size_t)grow * N + tx * TN + 2 * j) =
                    make_float2(x, y);
            }
        }
    }
}

// ---------------- launch ----------------------------------------------------
extern "C" void kernel_launch(void* const* d_in, const int* in_sizes, int n_in,
                              void* d_out, int out_size) {
    const float* feat = (const float*)d_in[0];
    const int*   src  = (const int*)d_in[1];
    const int*   dst  = (const int*)d_in[2];
    const float* Ws0 = (const float*)d_in[3];  const float* bs0 = (const float*)d_in[4];
    const float* Wn0 = (const float*)d_in[5];  const float* bn0 = (const float*)d_in[6];
    const float* Ws1 = (const float*)d_in[7];  const float* bs1 = (const float*)d_in[8];
    const float* Wn1 = (const float*)d_in[9];  const float* bn1 = (const float*)d_in[10];
    const float* Ws2 = (const float*)d_in[11]; const float* bs2 = (const float*)d_in[12];
    const float* Wn2 = (const float*)d_in[13]; const float* bn2 = (const float*)d_in[14];
    const float* Wout = (const float*)d_in[15]; const float* bout = (const float*)d_in[16];
    float* out = (float*)d_out;

    const int ZB = (N_NODES + 255) / 256;
    const int EB = (N_EDGES + 255) / 256;
    const int AGG_B  = (N_NODES + 7) / 8;          // warp per node, 8 warps/block
    const int GEMM_B = (N_NODES + 127) / 128;

    // CSR build (once per call, reused by all 3 layers)
    k_zero_deg<<<ZB, 256>>>();
    k_count<<<EB, 256>>>(dst);
    k_scan<<<1, 1024>>>();
    k_fill<<<EB, 256>>>(src, dst);

    // layer 0
    k_aggregate<<<AGG_B, 256>>>(BUF_EXT, feat);
    k_gemm<256, 128, 128, 128, 16, 8, 8, true, true>
        <<<GEMM_B, 256>>>(BUF_EXT, feat, Ws0, Wn0, bs0, bn0, BUF_A, nullptr, N_NODES);
    // layer 1
    k_aggregate<<<AGG_B, 256>>>(BUF_A, nullptr);
    k_gemm<256, 128, 128, 128, 16, 8, 8, true, true>
        <<<GEMM_B, 256>>>(BUF_A, nullptr, Ws1, Wn1, bs1, bn1, BUF_B, nullptr, N_NODES);
    // layer 2 (no relu)
    k_aggregate<<<AGG_B, 256>>>(BUF_B, nullptr);
    k_gemm<256, 128, 128, 128, 16, 8, 8, true, false>
        <<<GEMM_B, 256>>>(BUF_B, nullptr, Ws2, Wn2, bs2, bn2, BUF_A, nullptr, N_NODES);
    // final projection: [100K,128] @ [128,64] + b
    k_gemm<128, 64, 128, 64, 16, 8, 4, false, false>
        <<<GEMM_B, 256>>>(BUF_A, nullptr, Wout, Wout, bout, bout, BUF_EXT, out, N_NODES);
}

// round 6
// speedup vs baseline: 1.1806x; 1.1806x over previous
#include <cuda_runtime.h>
#include <cstddef>

#define N_NODES 100000
#define N_EDGES 600000
#define FEAT    128
#define OUTD    64
#define NCHUNK  ((N_NODES + 1023) / 1024)   // 98

// ---------------- scratch (device globals; no allocation allowed) ----------
__device__ __align__(128) float g_bufA[(size_t)N_NODES * FEAT];
__device__ __align__(128) float g_bufB[(size_t)N_NODES * FEAT];
__device__ __align__(128) float g_hn  [(size_t)N_NODES * FEAT];
__device__ int g_deg[N_NODES];
__device__ int g_rowptr[N_NODES + 1];
__device__ int g_cursor[N_NODES];
__device__ int g_csr[N_EDGES];
__device__ int g_blocksum[NCHUNK];
__device__ int g_blockoff[NCHUNK];

// buffer selectors (resolved device-side; keeps kernel_launch API-free)
#define BUF_EXT 0   // use the passed-in external pointer
#define BUF_A   1
#define BUF_B   2

__device__ __forceinline__ const float* sel_src(int sel, const float* ext) {
    if (sel == BUF_A) return g_bufA;
    if (sel == BUF_B) return g_bufB;
    return ext;
}
__device__ __forceinline__ float* sel_dst(int sel, float* ext) {
    if (sel == BUF_A) return g_bufA;
    if (sel == BUF_B) return g_bufB;
    return ext;
}

// ---------------- small helpers -------------------------------------------
__device__ __forceinline__ unsigned long long pack2(float a, float b) {
    unsigned long long r;
    asm("mov.b64 %0, {%1,%2};" : "=l"(r) : "f"(a), "f"(b));
    return r;
}
__device__ __forceinline__ void ffma2(unsigned long long& d,
                                      unsigned long long a,
                                      unsigned long long b) {
    asm("fma.rn.f32x2 %0, %1, %2, %0;" : "+l"(d) : "l"(a), "l"(b));
}

// ---------------- CSR construction ----------------------------------------
__global__ void k_zero_deg() {
    int i = blockIdx.x * blockDim.x + threadIdx.x;
    if (i < N_NODES) g_deg[i] = 0;
}

__global__ void k_count(const int* __restrict__ dst) {
    int e = blockIdx.x * blockDim.x + threadIdx.x;
    if (e < N_EDGES) atomicAdd(&g_deg[dst[e]], 1);
}

// phase 1: per-1024-chunk exclusive scan (98 blocks in parallel, one wave)
__global__ __launch_bounds__(1024) void k_scan1() {
    __shared__ int sh[1024];
    int tid = threadIdx.x;
    int i = blockIdx.x * 1024 + tid;
    int v = (i < N_NODES) ? g_deg[i] : 0;
    sh[tid] = v;
    __syncthreads();
#pragma unroll
    for (int off = 1; off < 1024; off <<= 1) {
        int t = (tid >= off) ? sh[tid - off] : 0;
        __syncthreads();
        sh[tid] += t;
        __syncthreads();
    }
    if (i < N_NODES) g_rowptr[i] = sh[tid] - v;   // chunk-local exclusive
    if (tid == 1023) g_blocksum[blockIdx.x] = sh[1023];
}

// phase 2: scan the 98 chunk sums (one tiny block)
__global__ void k_scan2() {
    __shared__ int sh[128];
    int tid = threadIdx.x;
    int v = (tid < NCHUNK) ? g_blocksum[tid] : 0;
    sh[tid] = v;
    __syncthreads();
#pragma unroll
    for (int off = 1; off < 128; off <<= 1) {
        int t = (tid >= off) ? sh[tid - off] : 0;
        __syncthreads();
        sh[tid] += t;
        __syncthreads();
    }
    if (tid < NCHUNK) g_blockoff[tid] = sh[tid] - v;  // exclusive chunk offset
    if (tid == NCHUNK - 1) g_rowptr[N_NODES] = sh[tid];
}

// phase 3: add chunk offsets; materialize rowptr + cursor
__global__ void k_scan3() {
    int i = blockIdx.x * blockDim.x + threadIdx.x;
    if (i < N_NODES) {
        int r = g_rowptr[i] + g_blockoff[i >> 10];
        g_rowptr[i] = r;
        g_cursor[i] = r;
    }
}

__global__ void k_fill(const int* __restrict__ src, const int* __restrict__ dst) {
    int e = blockIdx.x * blockDim.x + threadIdx.x;
    if (e < N_EDGES) {
        int p = atomicAdd(&g_cursor[dst[e]], 1);
        g_csr[p] = src[e];
    }
}

// ---------------- neighbor mean aggregation (warp per node) ----------------
__global__ void k_aggregate(int h_sel, const float* __restrict__ h_ext) {
    const float* __restrict__ h = sel_src(h_sel, h_ext);
    int node = (blockIdx.x * blockDim.x + threadIdx.x) >> 5;
    if (node >= N_NODES) return;
    int lane = threadIdx.x & 31;
    int beg = g_rowptr[node], end = g_rowptr[node + 1];
    float4 acc = make_float4(0.f, 0.f, 0.f, 0.f);
    for (int e = beg; e < end; e++) {
        int s = g_csr[e];
        float4 v = ((const float4*)(h + (size_t)s * FEAT))[lane];
        acc.x += v.x; acc.y += v.y; acc.z += v.z; acc.w += v.w;
    }
    float inv = 1.0f / fmaxf((float)(end - beg), 1.0f);
    acc.x *= inv; acc.y *= inv; acc.z *= inv; acc.w *= inv;
    ((float4*)(g_hn + (size_t)node * FEAT))[lane] = acc;
}

// ---------------- fused (dual-)GEMM + bias (+ReLU) -------------------------
// C[M,N] = act( A1@B1 (+ hn@B2) + bias1 (+ bias2) )
// B matrices are [K, N] row-major. Requires BN == N.
template <int KTOT, int N, int BM, int BN, int BK, int TM, int TN, bool DUAL, bool RELU>
__global__ __launch_bounds__(256)
void k_gemm(int a1_sel, const float* __restrict__ A1_ext,
            const float* __restrict__ B1, const float* __restrict__ B2,
            const float* __restrict__ bias1, const float* __restrict__ bias2,
            int c_sel, float* __restrict__ C_ext, int M) {
    constexpr int K  = DUAL ? KTOT / 2 : KTOT;   // per-matrix K
    constexpr int TX = BN / TN;                   // threads along n
    constexpr int TY = BM / TM;                   // threads along m
    static_assert(TX * TY == 256, "thread count mismatch");
    static_assert(BN == N, "BN must equal N");
    static_assert(K % BK == 0, "K % BK");

    const float* __restrict__ A1 = sel_src(a1_sel, A1_ext);
    float* __restrict__ C = sel_dst(c_sel, C_ext);

    __shared__ __align__(16) float As[BK * BM];   // As[k][m]
    __shared__ __align__(16) float Bs[BK * BN];   // Bs[k][n]

    const int tid = threadIdx.x;
    const int tx = tid % TX, ty = tid / TX;
    const int row0 = blockIdx.x * BM;

    unsigned long long acc[TM][TN / 2];
#pragma unroll
    for (int m = 0; m < TM; m++)
#pragma unroll
        for (int j = 0; j < TN / 2; j++) acc[m][j] = 0ull;

#pragma unroll 1
    for (int k0 = 0; k0 < KTOT; k0 += BK) {
        const bool first = (!DUAL) || (k0 < K);
        const float* __restrict__ A = first ? A1 : (const float*)g_hn;
        const float* __restrict__ B = first ? B1 : B2;
        const int ka = first ? k0 : (k0 - K);

        // A tile: BM x BK -> As (k-major). 4 lanes per row, 16B per lane.
#pragma unroll
        for (int i = 0; i < (BM * BK / 4) / 256; i++) {
            int idx = i * 256 + tid;
            int kq  = idx & 3;        // which float4 within the BK=16 chunk
            int row = idx >> 2;       // 0..BM-1
            float4 v = make_float4(0.f, 0.f, 0.f, 0.f);
            if (row0 + row < M)
                v = *(const float4*)(A + (size_t)(row0 + row) * K + ka + kq * 4);
            As[(kq * 4 + 0) * BM + row] = v.x;
            As[(kq * 4 + 1) * BM + row] = v.y;
            As[(kq * 4 + 2) * BM + row] = v.z;
            As[(kq * 4 + 3) * BM + row] = v.w;
        }
        // B tile: BK x BN, coalesced, row stride N
#pragma unroll
        for (int i = 0; i < (BK * BN / 4) / 256; i++) {
            int idx = i * 256 + tid;
            int kr  = idx / (BN / 4);
            int n4  = idx % (BN / 4);
            float4 v = *(const float4*)(B + (size_t)(ka + kr) * N + n4 * 4);
            ((float4*)Bs)[idx] = v;
        }
        __syncthreads();

#pragma unroll
        for (int k = 0; k < BK; k++) {
            // a fragment: TM scalars, duplicated into f32x2 pairs
            unsigned long long ap[TM];
#pragma unroll
            for (int q = 0; q < TM / 4; q++) {
                float4 a4 = *(const float4*)&As[k * BM + ty * TM + 4 * q];
                ap[4 * q + 0] = pack2(a4.x, a4.x);
                ap[4 * q + 1] = pack2(a4.y, a4.y);
                ap[4 * q + 2] = pack2(a4.z, a4.z);
                ap[4 * q + 3] = pack2(a4.w, a4.w);
            }
            // b fragment: consecutive float pairs ARE packed f32x2 (free)
            unsigned long long bp[TN / 2];
#pragma unroll
            for (int j = 0; j < TN / 4; j++) {
                ulonglong2 t = *(const ulonglong2*)&Bs[k * BN + tx * TN + 4 * j];
                bp[2 * j + 0] = t.x;
                bp[2 * j + 1] = t.y;
            }
#pragma unroll
            for (int m = 0; m < TM; m++)
#pragma unroll
                for (int j = 0; j < TN / 2; j++)
                    ffma2(acc[m][j], ap[m], bp[j]);
        }
        __syncthreads();
    }

    // epilogue: bias (+relu), packed float2 stores
    float bs[TN];
#pragma unroll
    for (int t = 0; t < TN; t++) {
        int col = tx * TN + t;
        bs[t] = bias1[col] + (DUAL ? bias2[col] : 0.0f);
    }
#pragma unroll
    for (int m = 0; m < TM; m++) {
        int grow = row0 + ty * TM + m;
        if (grow < M) {
#pragma unroll
            for (int j = 0; j < TN / 2; j++) {
                union { unsigned long long u; float2 f; } cv;
                cv.u = acc[m][j];
                float x = cv.f.x + bs[2 * j];
                float y = cv.f.y + bs[2 * j + 1];
                if (RELU) { x = fmaxf(x, 0.f); y = fmaxf(y, 0.f); }
                *(float2*)(C + (size_t)grow * N + tx * TN + 2 * j) =
                    make_float2(x, y);
            }
        }
    }
}

// ---------------- launch ----------------------------------------------------
extern "C" void kernel_launch(void* const* d_in, const int* in_sizes, int n_in,
                              void* d_out, int out_size) {
    const float* feat = (const float*)d_in[0];
    const int*   src  = (const int*)d_in[1];
    const int*   dst  = (const int*)d_in[2];
    const float* Ws0 = (const float*)d_in[3];  const float* bs0 = (const float*)d_in[4];
    const float* Wn0 = (const float*)d_in[5];  const float* bn0 = (const float*)d_in[6];
    const float* Ws1 = (const float*)d_in[7];  const float* bs1 = (const float*)d_in[8];
    const float* Wn1 = (const float*)d_in[9];  const float* bn1 = (const float*)d_in[10];
    const float* Ws2 = (const float*)d_in[11]; const float* bs2 = (const float*)d_in[12];
    const float* Wn2 = (const float*)d_in[13]; const float* bn2 = (const float*)d_in[14];
    const float* Wout = (const float*)d_in[15]; const float* bout = (const float*)d_in[16];
    float* out = (float*)d_out;

    const int ZB = (N_NODES + 255) / 256;
    const int EB = (N_EDGES + 255) / 256;
    const int AGG_B  = (N_NODES + 7) / 8;          // warp per node, 8 warps/block
    const int GEMM_B = (N_NODES + 127) / 128;

    // CSR build (once per call, reused by all 3 layers)
    k_zero_deg<<<ZB, 256>>>();
    k_count<<<EB, 256>>>(dst);
    k_scan1<<<NCHUNK, 1024>>>();
    k_scan2<<<1, 128>>>();
    k_scan3<<<ZB, 256>>>();
    k_fill<<<EB, 256>>>(src, dst);

    // layer 0
    k_aggregate<<<AGG_B, 256>>>(BUF_EXT, feat);
    k_gemm<256, 128, 128, 128, 16, 8, 8, true, true>
        <<<GEMM_B, 256>>>(BUF_EXT, feat, Ws0, Wn0, bs0, bn0, BUF_A, nullptr, N_NODES);
    // layer 1
    k_aggregate<<<AGG_B, 256>>>(BUF_A, nullptr);
    k_gemm<256, 128, 128, 128, 16, 8, 8, true, true>
        <<<GEMM_B, 256>>>(BUF_A, nullptr, Ws1, Wn1, bs1, bn1, BUF_B, nullptr, N_NODES);
    // layer 2 (no relu)
    k_aggregate<<<AGG_B, 256>>>(BUF_B, nullptr);
    k_gemm<256, 128, 128, 128, 16, 8, 8, true, false>
        <<<GEMM_B, 256>>>(BUF_B, nullptr, Ws2, Wn2, bs2, bn2, BUF_A, nullptr, N_NODES);
    // final projection: [100K,128] @ [128,64] + b
    k_gemm<128, 64, 128, 64, 16, 8, 4, false, false>
        <<<GEMM_B, 256>>>(BUF_A, nullptr, Wout, Wout, bout, bout, BUF_EXT, out, N_NODES);
}